// round 6
// baseline (speedup 1.0000x reference)
#include <cuda_runtime.h>
#include <cstddef>

#define BB 2048
#define NN 512
#define XX 32
#define HH 64
#define TILE_B 8
#define THREADS 128
#define NBLK (BB / TILE_B)   /* 256 */
#define HPITCH 12            /* 48B pitch: 16B-aligned */

__device__ __forceinline__ unsigned long long pack2(float v) {
    unsigned long long r;
    asm("mov.b64 %0, {%1, %1};" : "=l"(r) : "f"(v));
    return r;
}
__device__ __forceinline__ unsigned long long fma2(unsigned long long a,
                                                   unsigned long long b,
                                                   unsigned long long c) {
    unsigned long long d;
    asm("fma.rn.f32x2 %0, %1, %2, %3;" : "=l"(d) : "l"(a), "l"(b), "l"(c));
    return d;
}
__device__ __forceinline__ void unpack2(unsigned long long v, float& lo, float& hi) {
    asm("mov.b64 {%0, %1}, %2;" : "=f"(lo), "=f"(hi) : "l"(v));
}

__device__ __forceinline__ float sigmoidf_fast(float x) {
    return __fdividef(1.0f, 1.0f + __expf(-x));
}
__device__ __forceinline__ float tanhf_fast(float x) {
    return __fdividef(2.0f, 1.0f + __expf(-2.0f * x)) - 1.0f;
}

__global__ void __launch_bounds__(THREADS, 2)
timelstm_kernel(const float* __restrict__ x,
                const float* __restrict__ ig_w_c, const float* __restrict__ ig_w_h,
                const float* __restrict__ ig_w_x, const float* __restrict__ ig_b,
                const float* __restrict__ fg_w_c, const float* __restrict__ fg_w_h,
                const float* __restrict__ fg_w_x, const float* __restrict__ fg_b,
                const float* __restrict__ in_w_h, const float* __restrict__ in_w_x,
                const float* __restrict__ in_b,
                const float* __restrict__ og_w_cn, const float* __restrict__ og_w_h,
                const float* __restrict__ og_w_x, const float* __restrict__ og_b,
                float* __restrict__ out)
{
    // ping-pong state buffers: [buf][k][row], 16B-aligned rows
    __shared__ __align__(16) float h_sh[2][HH * HPITCH];
    __shared__ __align__(16) float x_sh[2][XX * HPITCH];

    const int tid = threadIdx.x;
    const int b0  = blockIdx.x * TILE_B;
    const int p   = tid & 1;            // gate pair: 0 -> (ig,fg), 1 -> (in,og)
    const int hid = (tid >> 1) & 63;    // output channel (partner = lane^1)

    // ---- two full weight rows per thread ----
    const float *Wh0, *Wx0, *Bv0, *Wh1, *Wx1, *Bv1;
    if (p == 0) { Wh0 = ig_w_h; Wx0 = ig_w_x; Bv0 = ig_b;
                  Wh1 = fg_w_h; Wx1 = fg_w_x; Bv1 = fg_b; }
    else        { Wh0 = in_w_h; Wx0 = in_w_x; Bv0 = in_b;
                  Wh1 = og_w_h; Wx1 = og_w_x; Bv1 = og_b; }

    float w0[96], w1[96];
    #pragma unroll
    for (int j = 0; j < 32; j++) { w0[j] = Wx0[hid * XX + j]; w1[j] = Wx1[hid * XX + j]; }
    #pragma unroll
    for (int j = 0; j < 64; j++) { w0[32 + j] = Wh0[hid * HH + j]; w1[32 + j] = Wh1[hid * HH + j]; }
    const float bias0 = Bv0[hid];
    const float bias1 = Bv1[hid];
    const float wic = ig_w_c[hid];
    const float wfc = fg_w_c[hid];
    const float woc = og_w_cn[hid];

    // zero h buffer 0 (read at t=0)
    for (int i = tid; i < HH * HPITCH; i += THREADS) h_sh[0][i] = 0.0f;

    // cm state in registers: rows 4p..4p+3, channel hid
    float cm[4] = {0.0f, 0.0f, 0.0f, 0.0f};

    // ---- x prefetch: 2 values/thread/step (8 rows x 32 k) ----
    const int xr = tid >> 5;   // rows xr and xr+4
    const int xk = tid & 31;
    const float* xp0 = x + ((size_t)(b0 + xr) * NN) * XX + xk;
    const float* xp1 = x + ((size_t)(b0 + xr + 4) * NN) * XX + xk;
    float xv0 = xp0[0], xv1 = xp1[0];

    for (int t = 0; t < NN; t++) {
        const int buf = t & 1;
        // deposit prefetched x_t into this step's buffer
        x_sh[buf][xk * HPITCH + xr]     = xv0;
        x_sh[buf][xk * HPITCH + xr + 4] = xv1;
        __syncthreads();   // sole barrier: x_t deposits + previous h writes visible

        if (t + 1 < NN) {
            xv0 = xp0[(size_t)(t + 1) * XX];
            xv1 = xp1[(size_t)(t + 1) * XX];
        }

        // ---- phase A: 8 rows x 2 gates, packed f32x2 ----
        unsigned long long a0[4], a1[4];
        {
            unsigned long long b0p = pack2(bias0), b1p = pack2(bias1);
            #pragma unroll
            for (int i = 0; i < 4; i++) { a0[i] = b0p; a1[i] = b1p; }
        }
        #pragma unroll
        for (int k = 0; k < XX; k++) {
            const ulonglong2* ptr =
                reinterpret_cast<const ulonglong2*>(&x_sh[buf][k * HPITCH]);
            ulonglong2 v0 = ptr[0], v1 = ptr[1];
            unsigned long long u0 = pack2(w0[k]), u1 = pack2(w1[k]);
            a0[0] = fma2(v0.x, u0, a0[0]); a0[1] = fma2(v0.y, u0, a0[1]);
            a0[2] = fma2(v1.x, u0, a0[2]); a0[3] = fma2(v1.y, u0, a0[3]);
            a1[0] = fma2(v0.x, u1, a1[0]); a1[1] = fma2(v0.y, u1, a1[1]);
            a1[2] = fma2(v1.x, u1, a1[2]); a1[3] = fma2(v1.y, u1, a1[3]);
        }
        #pragma unroll
        for (int k = 0; k < HH; k++) {
            const ulonglong2* ptr =
                reinterpret_cast<const ulonglong2*>(&h_sh[buf][k * HPITCH]);
            ulonglong2 v0 = ptr[0], v1 = ptr[1];
            unsigned long long u0 = pack2(w0[32 + k]), u1 = pack2(w1[32 + k]);
            a0[0] = fma2(v0.x, u0, a0[0]); a0[1] = fma2(v0.y, u0, a0[1]);
            a0[2] = fma2(v1.x, u0, a0[2]); a0[3] = fma2(v1.y, u0, a0[3]);
            a1[0] = fma2(v0.x, u1, a1[0]); a1[1] = fma2(v0.y, u1, a1[1]);
            a1[2] = fma2(v1.x, u1, a1[2]); a1[3] = fma2(v1.y, u1, a1[3]);
        }

        // ---- gate exchange with partner lane (lane^1): 4x 64-bit shfl ----
        // acc pair i covers rows 2i,2i+1. This thread's rows: pairs 2p,2p+1.
        // Send the pairs the partner needs (its rows), receive ours.
        unsigned long long sA0 = p ? a0[0] : a0[2];
        unsigned long long sA1 = p ? a0[1] : a0[3];
        unsigned long long sB0 = p ? a1[0] : a1[2];
        unsigned long long sB1 = p ? a1[1] : a1[3];
        unsigned long long rA0 = __shfl_xor_sync(0xffffffffu, sA0, 1);
        unsigned long long rA1 = __shfl_xor_sync(0xffffffffu, sA1, 1);
        unsigned long long rB0 = __shfl_xor_sync(0xffffffffu, sB0, 1);
        unsigned long long rB1 = __shfl_xor_sync(0xffffffffu, sB1, 1);

        // canonical gate pre-activations for THIS thread's rows (4p..4p+3)
        unsigned long long IG0 = p ? rA0 : a0[0];
        unsigned long long IG1 = p ? rA1 : a0[1];
        unsigned long long FG0 = p ? rB0 : a1[0];
        unsigned long long FG1 = p ? rB1 : a1[1];
        unsigned long long IN0 = p ? a0[2] : rA0;
        unsigned long long IN1 = p ? a0[3] : rA1;
        unsigned long long OG0 = p ? a1[2] : rB0;
        unsigned long long OG1 = p ? a1[3] : rB1;

        float igv[4], fgv[4], inv[4], ogv[4];
        unpack2(IG0, igv[0], igv[1]); unpack2(IG1, igv[2], igv[3]);
        unpack2(FG0, fgv[0], fgv[1]); unpack2(FG1, fgv[2], fgv[3]);
        unpack2(IN0, inv[0], inv[1]); unpack2(IN1, inv[2], inv[3]);
        unpack2(OG0, ogv[0], ogv[1]); unpack2(OG1, ogv[2], ogv[3]);

        // ---- phase B: 4 rows, cm in registers, no barrier ----
        float hv[4];
        #pragma unroll
        for (int j = 0; j < 4; j++) {
            const float ig  = sigmoidf_fast(wic * cm[j] + igv[j]);
            const float fg  = sigmoidf_fast(wfc * cm[j] + fgv[j]);
            const float inn = tanhf_fast(inv[j]);
            const float cmn = fg * cm[j] + ig * inn;
            const float og  = sigmoidf_fast(woc * cmn + ogv[j]);
            hv[j] = og * tanhf_fast(cmn);
            cm[j] = cmn;
        }
        // write h for next step into alternate buffer: h_sh[buf^1][hid][4p..4p+3]
        *reinterpret_cast<float4*>(&h_sh[buf ^ 1][hid * HPITCH + 4 * p]) =
            make_float4(hv[0], hv[1], hv[2], hv[3]);

        if (t == NN - 1) {
            #pragma unroll
            for (int j = 0; j < 4; j++)
                out[(size_t)(b0 + 4 * p + j) * HH + hid] = hv[j];
        }
        // no second barrier: next step writes only the alternate buffers
    }
}

extern "C" void kernel_launch(void* const* d_in, const int* in_sizes, int n_in,
                              void* d_out, int out_size) {
    const float* x       = (const float*)d_in[0];
    const float* ig_w_c  = (const float*)d_in[1];
    const float* ig_w_h  = (const float*)d_in[2];
    const float* ig_w_x  = (const float*)d_in[3];
    const float* ig_b    = (const float*)d_in[4];
    const float* fg_w_c  = (const float*)d_in[5];
    const float* fg_w_h  = (const float*)d_in[6];
    const float* fg_w_x  = (const float*)d_in[7];
    const float* fg_b    = (const float*)d_in[8];
    const float* in_w_h  = (const float*)d_in[9];
    const float* in_w_x  = (const float*)d_in[10];
    const float* in_b    = (const float*)d_in[11];
    const float* og_w_cn = (const float*)d_in[12];
    const float* og_w_h  = (const float*)d_in[13];
    const float* og_w_x  = (const float*)d_in[14];
    const float* og_b    = (const float*)d_in[15];
    float* out = (float*)d_out;

    timelstm_kernel<<<NBLK, THREADS>>>(
        x, ig_w_c, ig_w_h, ig_w_x, ig_b,
        fg_w_c, fg_w_h, fg_w_x, fg_b,
        in_w_h, in_w_x, in_b,
        og_w_cn, og_w_h, og_w_x, og_b, out);
}